// round 17
// baseline (speedup 1.0000x reference)
#include <cuda_runtime.h>

#define NU 50000
#define NI 100000
#define NN 150000
#define NE 2400000
#define N_LAYERS 3
#define KE 64   // edges per warp in segmented spmm (NE % KE == 0)
#define SP 72   // smem pitch (floats) for dense tiles

// ---- scratch (device globals; no allocation) ----
__device__ float g_ego0[NN * 64];
__device__ float g_ego1[NN * 64];
__device__ float g_side[NN * 64];
__device__ int g_cnt[NN];  // histogram (always returned to zero)
__device__ int g_cur[NN];  // scatter cursors
// packed edge, dst-sorted: bits[36:64)=val(f32>>4), [18:36)=dst, [0:18)=src
__device__ unsigned long long g_edges[NE];

// streaming store (evict-first) for never-re-read outputs
__device__ __forceinline__ void stcs4(float* p, float4 v) {
    asm volatile("st.global.cs.v4.f32 [%0], {%1,%2,%3,%4};"
                 :: "l"(p), "f"(v.x), "f"(v.y), "f"(v.z), "f"(v.w)
                 : "memory");
}
__device__ __forceinline__ void stcs2(float* p, float a, float b) {
    asm volatile("st.global.cs.v2.f32 [%0], {%1,%2};"
                 :: "l"(p), "f"(a), "f"(b) : "memory");
}

// ---------------------------------------------------------------------------
__global__ void zero_cnt_kernel() {
    int i = blockIdx.x * blockDim.x + threadIdx.x;
    if (i < NN) g_cnt[i] = 0;
}

// init + hist fused: NN*16 threads == NE threads exactly.
__global__ void init_hist_kernel(const float4* __restrict__ ue,
                                 const float4* __restrict__ ie,
                                 float4* __restrict__ out4,
                                 const int* __restrict__ edst) {
    int idx = blockIdx.x * blockDim.x + threadIdx.x;
    if (idx >= NE) return;  // NE == NN*16
    atomicAdd(&g_cnt[edst[idx]], 1);
    int row = idx >> 4;
    int c = idx & 15;
    float4 v = (row < NU) ? ue[row * 16 + c] : ie[(row - NU) * 16 + c];
    ((float4*)g_ego0)[idx] = v;
    stcs4((float*)(out4 + row * 64 + c), v);
}

// scan: prefix of g_cnt -> g_cur cursors; re-zeroes g_cnt.
__global__ void scan_kernel() {  // <<<1, 1024>>>
    __shared__ int part[1024];
    int t = threadIdx.x;
    const int CH = (NN + 1023) / 1024;  // 147
    int beg = t * CH;
    int end = min(beg + CH, NN);
    int s = 0;
    for (int i0 = beg; i0 < end; i0 += 8) {
        int c[8];
#pragma unroll
        for (int u = 0; u < 8; u++)
            c[u] = (i0 + u < end) ? g_cnt[i0 + u] : 0;
#pragma unroll
        for (int u = 0; u < 8; u++) s += c[u];
    }
    part[t] = s;
    __syncthreads();
    for (int o = 1; o < 1024; o <<= 1) {
        int v = (t >= o) ? part[t - o] : 0;
        __syncthreads();
        part[t] += v;
        __syncthreads();
    }
    int pre = (t == 0) ? 0 : part[t - 1];
    for (int i0 = beg; i0 < end; i0 += 8) {
        int c[8];
#pragma unroll
        for (int u = 0; u < 8; u++)
            c[u] = (i0 + u < end) ? g_cnt[i0 + u] : 0;
#pragma unroll
        for (int u = 0; u < 8; u++) {
            if (i0 + u < end) {
                g_cur[i0 + u] = pre;
                g_cnt[i0 + u] = 0;
                pre += c[u];
            }
        }
    }
}

__global__ void scatter_kernel(const int* __restrict__ esrc,
                               const int* __restrict__ edst,
                               const float* __restrict__ ev) {
    int e = blockIdx.x * blockDim.x + threadIdx.x;
    if (e >= NE) return;
    int d = edst[e];
    int pos = atomicAdd(&g_cur[d], 1);
    unsigned vb = __float_as_uint(ev[e]);
    g_edges[pos] = ((unsigned long long)(vb >> 4) << 36) |
                   ((unsigned long long)(unsigned)d << 18) |
                   (unsigned long long)(unsigned)esrc[e];
}

// ---------------------------------------------------------------------------
// segmented-reduction SpMM (unchanged; near its L2 floor)
// ---------------------------------------------------------------------------
__device__ __forceinline__ void flush4(int row, int l16, float4 a) {
    float* p = g_side + (size_t)row * 64 + l16 * 4;
    asm volatile("red.global.add.v4.f32 [%0], {%1,%2,%3,%4};"
                 :: "l"(p), "f"(a.x), "f"(a.y), "f"(a.z), "f"(a.w)
                 : "memory");
}

__global__ void __launch_bounds__(256, 3) spmm_kernel(
    const float* __restrict__ egoIn) {
    int gw = (blockIdx.x * blockDim.x + threadIdx.x) >> 5;
    if (gw >= NE / KE) return;
    int lane = threadIdx.x & 31;
    int h = lane >> 4;
    int l16 = lane & 15;
    const float4* ego4 = (const float4*)egoIn;
    const ulonglong2* ep = (const ulonglong2*)(g_edges + (size_t)gw * KE);

    unsigned long long my[8];
#pragma unroll
    for (int u = 0; u < 8; u++) {
        ulonglong2 p = __ldg(ep + u);
        my[u] = h ? p.y : p.x;
    }
    float4 acc = make_float4(0.f, 0.f, 0.f, 0.f);
    int cur = (int)((my[0] >> 18) & 0x3FFFFu);

#pragma unroll
    for (int j = 0; j < KE / 16; j++) {
        float4 x[8];
#pragma unroll
        for (int u = 0; u < 8; u++) {
            unsigned src = (unsigned)my[u] & 0x3FFFFu;
            x[u] = __ldcg(&ego4[(size_t)src * 16 + l16]);
        }
        unsigned long long nxt[8];
        if (j < KE / 16 - 1) {
#pragma unroll
            for (int u = 0; u < 8; u++) {
                ulonglong2 p = __ldg(ep + (j + 1) * 8 + u);
                nxt[u] = h ? p.y : p.x;
            }
        }
#pragma unroll
        for (int u = 0; u < 8; u++) {
            int d = (int)((my[u] >> 18) & 0x3FFFFu);
            if (d != cur) {
                flush4(cur, l16, acc);
                acc = make_float4(0.f, 0.f, 0.f, 0.f);
                cur = d;
            }
            float v = __uint_as_float((unsigned)(my[u] >> 36) << 4);
            acc.x = fmaf(v, x[u].x, acc.x);
            acc.y = fmaf(v, x[u].y, acc.y);
            acc.z = fmaf(v, x[u].z, acc.z);
            acc.w = fmaf(v, x[u].w, acc.w);
        }
        if (j < KE / 16 - 1) {
#pragma unroll
            for (int u = 0; u < 8; u++) my[u] = nxt[u];
        }
    }
    flush4(cur, l16, acc);
}

// ---------------------------------------------------------------------------
// tf32 helpers
// ---------------------------------------------------------------------------
__device__ __forceinline__ unsigned tf32of(float x) {
    unsigned r;
    asm("cvt.rna.tf32.f32 %0, %1;" : "=r"(r) : "f"(x));
    return r;
}
__device__ __forceinline__ void split_tf32(float x, unsigned& hi, unsigned& lo) {
    hi = tf32of(x);
    float res = x - __uint_as_float(hi);
    lo = tf32of(res);
}
__device__ __forceinline__ void mma_tf32(float c[4], const unsigned a[4],
                                         const unsigned b[2]) {
    asm volatile(
        "mma.sync.aligned.m16n8k8.row.col.f32.tf32.tf32.f32 "
        "{%0,%1,%2,%3}, {%4,%5,%6,%7}, {%8,%9}, {%0,%1,%2,%3};"
        : "+f"(c[0]), "+f"(c[1]), "+f"(c[2]), "+f"(c[3])
        : "r"(a[0]), "r"(a[1]), "r"(a[2]), "r"(a[3]), "r"(b[0]), "r"(b[1]));
}

// ---------------------------------------------------------------------------
// dense layer, tensor-core version. 64-row tile, 256 threads, occ 2.
//   warps 0-3: GC matrix (side @ Wgc^T), rowtile = warp
//   warps 4-7: Bi matrix ((ego*side) @ Wbi^T), rowtile = warp-4
// tf32 mma m16n8k8 with 3-term hi/lo compensation (rel err ~1e-6).
// Bi warps exchange leaky'd values via smem; GC warps add + l2norm + store.
// Re-zeroes g_side rows (fused memset). Streaming `out` stores.
// ---------------------------------------------------------------------------
__global__ void __launch_bounds__(256, 2) dense_kernel(
    const float* __restrict__ Wgc, const float* __restrict__ bgc,
    const float* __restrict__ Wbi, const float* __restrict__ bbi,
    const float* __restrict__ egoIn, float* __restrict__ egoOut,
    int layer, float* __restrict__ out) {
    extern __shared__ float sm[];
    float* sX = sm;                // side      [64][SP]
    float* sP = sm + 64 * SP;      // ego*side  [64][SP]
    float* sWg = sm + 128 * SP;    // Wgc^T [k][j] pitch SP
    float* sWb = sm + 192 * SP;    // Wbi^T

    const float* Wg = Wgc + layer * 4096;
    const float* Wb = Wbi + layer * 4096;
    int tid = threadIdx.x;
    int row0 = blockIdx.x * 64;
    bool writeEgo = (layer + 1 < N_LAYERS);

    // W transpose fill (lane j fastest -> conflict-free STS)
    for (int idx = tid; idx < 1024; idx += 256) {
        int j = idx & 63;
        int k4 = (idx >> 6) << 2;
        float4 wg = __ldg((const float4*)(Wg + j * 64 + k4));
        float4 wb = __ldg((const float4*)(Wb + j * 64 + k4));
        sWg[(k4 + 0) * SP + j] = wg.x;
        sWg[(k4 + 1) * SP + j] = wg.y;
        sWg[(k4 + 2) * SP + j] = wg.z;
        sWg[(k4 + 3) * SP + j] = wg.w;
        sWb[(k4 + 0) * SP + j] = wb.x;
        sWb[(k4 + 1) * SP + j] = wb.y;
        sWb[(k4 + 2) * SP + j] = wb.z;
        sWb[(k4 + 3) * SP + j] = wb.w;
    }
    // side + ego tiles (product at fill time)
    for (int idx = tid; idx < 1024; idx += 256) {
        int r = idx >> 4;
        int c = idx & 15;
        int row = row0 + r;
        float4 xs = make_float4(0.f, 0.f, 0.f, 0.f);
        float4 xe = xs;
        if (row < NN) {
            xs = __ldg(&((const float4*)g_side)[row * 16 + c]);
            xe = __ldg(&((const float4*)egoIn)[row * 16 + c]);
        }
        *(float4*)(sX + r * SP + c * 4) = xs;
        *(float4*)(sP + r * SP + c * 4) =
            make_float4(xs.x * xe.x, xs.y * xe.y, xs.z * xe.z, xs.w * xe.w);
    }
    __syncthreads();

    // re-zero this block's side rows for the next spmm
    {
        float4 z = make_float4(0.f, 0.f, 0.f, 0.f);
        for (int idx = tid; idx < 1024; idx += 256) {
            int r = idx >> 4;
            int c = idx & 15;
            int row = row0 + r;
            if (row < NN) ((float4*)g_side)[row * 16 + c] = z;
        }
    }

    int w = tid >> 5;
    int lane = tid & 31;
    int m = w >> 2;       // 0 = GC, 1 = Bi
    int rt = w & 3;       // row tile (16 rows)
    int gid = lane >> 2;  // 0..7
    int q = lane & 3;     // 0..3
    const float* sA = m ? sP : sX;
    const float* sW = m ? sWb : sWg;
    const float* bias = (m ? bbi : bgc) + layer * 64;

    float c[8][4];
#pragma unroll
    for (int jt = 0; jt < 8; jt++)
#pragma unroll
        for (int i = 0; i < 4; i++) c[jt][i] = 0.f;

    int ar0 = (rt * 16 + gid) * SP;
    int ar1 = (rt * 16 + gid + 8) * SP;
#pragma unroll
    for (int kt = 0; kt < 8; kt++) {
        int kb = kt * 8;
        unsigned ahi[4], alo[4];
        split_tf32(sA[ar0 + kb + q], ahi[0], alo[0]);
        split_tf32(sA[ar1 + kb + q], ahi[1], alo[1]);
        split_tf32(sA[ar0 + kb + 4 + q], ahi[2], alo[2]);
        split_tf32(sA[ar1 + kb + 4 + q], ahi[3], alo[3]);
#pragma unroll
        for (int jt = 0; jt < 8; jt++) {
            unsigned bhi[2], blo[2];
            split_tf32(sW[(kb + q) * SP + jt * 8 + gid], bhi[0], blo[0]);
            split_tf32(sW[(kb + 4 + q) * SP + jt * 8 + gid], bhi[1], blo[1]);
            mma_tf32(c[jt], ahi, bhi);
            mma_tf32(c[jt], ahi, blo);
            mma_tf32(c[jt], alo, bhi);
        }
    }

    // bias + leaky (per-thread values: rows gid / gid+8, cols jt*8+q*2, +1)
    float v[8][4];
#pragma unroll
    for (int jt = 0; jt < 8; jt++) {
        int j0 = jt * 8 + q * 2;
        float2 b2 = *(const float2*)(bias + j0);
        float t0 = c[jt][0] + b2.x;
        float t1 = c[jt][1] + b2.y;
        float t2 = c[jt][2] + b2.x;
        float t3 = c[jt][3] + b2.y;
        v[jt][0] = (t0 > 0.f) ? t0 : 0.01f * t0;
        v[jt][1] = (t1 > 0.f) ? t1 : 0.01f * t1;
        v[jt][2] = (t2 > 0.f) ? t2 : 0.01f * t2;
        v[jt][3] = (t3 > 0.f) ? t3 : 0.01f * t3;
    }
    __syncthreads();  // all GEMM smem reads done

    // Bi warps publish to exchange buffer (reuse sX region, pitch SP)
    if (m == 1) {
        int r0 = (rt * 16 + gid) * SP;
        int r1 = (rt * 16 + gid + 8) * SP;
#pragma unroll
        for (int jt = 0; jt < 8; jt++) {
            int j0 = jt * 8 + q * 2;
            sX[r0 + j0] = v[jt][0];
            sX[r0 + j0 + 1] = v[jt][1];
            sX[r1 + j0] = v[jt][2];
            sX[r1 + j0 + 1] = v[jt][3];
        }
    }
    __syncthreads();

    // GC warps: add Bi, l2norm, store
    if (m == 0) {
        int r0 = (rt * 16 + gid) * SP;
        int r1 = (rt * 16 + gid + 8) * SP;
        float u[8][4];
        float ss0 = 0.f, ss1 = 0.f;
#pragma unroll
        for (int jt = 0; jt < 8; jt++) {
            int j0 = jt * 8 + q * 2;
            u[jt][0] = v[jt][0] + sX[r0 + j0];
            u[jt][1] = v[jt][1] + sX[r0 + j0 + 1];
            u[jt][2] = v[jt][2] + sX[r1 + j0];
            u[jt][3] = v[jt][3] + sX[r1 + j0 + 1];
            ss0 += u[jt][0] * u[jt][0] + u[jt][1] * u[jt][1];
            ss1 += u[jt][2] * u[jt][2] + u[jt][3] * u[jt][3];
        }
        // reduce across q (lanes gid*4+0..3)
#pragma unroll
        for (int o = 1; o <= 2; o <<= 1) {
            ss0 += __shfl_xor_sync(0xffffffffu, ss0, o);
            ss1 += __shfl_xor_sync(0xffffffffu, ss1, o);
        }
        float inv0 = rsqrtf(fmaxf(ss0, 1e-24f));
        float inv1 = rsqrtf(fmaxf(ss1, 1e-24f));

        int row0g = row0 + rt * 16 + gid;
        int row1g = row0g + 8;
        int colbase = (layer + 1) * 64;
#pragma unroll
        for (int jt = 0; jt < 8; jt++) {
            int j0 = jt * 8 + q * 2;
            if (row0g < NN) {
                if (writeEgo)
                    *(float2*)(egoOut + (size_t)row0g * 64 + j0) =
                        make_float2(u[jt][0], u[jt][1]);
                stcs2(out + (size_t)row0g * 256 + colbase + j0,
                      u[jt][0] * inv0, u[jt][1] * inv0);
            }
            if (row1g < NN) {
                if (writeEgo)
                    *(float2*)(egoOut + (size_t)row1g * 64 + j0) =
                        make_float2(u[jt][2], u[jt][3]);
                stcs2(out + (size_t)row1g * 256 + colbase + j0,
                      u[jt][2] * inv1, u[jt][3] * inv1);
            }
        }
    }
}

// ---------------------------------------------------------------------------
extern "C" void kernel_launch(void* const* d_in, const int* in_sizes, int n_in,
                              void* d_out, int out_size) {
    const int* esrc = (const int*)d_in[0];
    const int* edst = (const int*)d_in[1];
    const float* ev = (const float*)d_in[2];
    const float* ue = (const float*)d_in[3];
    const float* ie = (const float*)d_in[4];
    const float* Wgc = (const float*)d_in[5];
    const float* bgc = (const float*)d_in[6];
    const float* Wbi = (const float*)d_in[7];
    const float* bbi = (const float*)d_in[8];
    float* out = (float*)d_out;

    void* e0 = nullptr;
    void* e1 = nullptr;
    cudaGetSymbolAddress(&e0, g_ego0);
    cudaGetSymbolAddress(&e1, g_ego1);
    float* bufs[2] = {(float*)e0, (float*)e1};

    int dsmem = 256 * SP * sizeof(float);  // 4 tiles x 64 rows x SP
    cudaFuncSetAttribute(dense_kernel,
                         cudaFuncAttributeMaxDynamicSharedMemorySize, dsmem);

    zero_cnt_kernel<<<(NN + 255) / 256, 256>>>();
    init_hist_kernel<<<(NE + 255) / 256, 256>>>(
        (const float4*)ue, (const float4*)ie, (float4*)out, edst);
    scan_kernel<<<1, 1024>>>();
    scatter_kernel<<<(NE + 255) / 256, 256>>>(esrc, edst, ev);

    int sgrid = (NE / KE * 32 + 255) / 256;
    int dgrid = (NN + 63) / 64;
    for (int l = 0; l < N_LAYERS; l++) {
        spmm_kernel<<<sgrid, 256>>>(bufs[l & 1]);
        dense_kernel<<<dgrid, 256, dsmem>>>(Wgc, bgc, Wbi, bbi,
                                            bufs[l & 1], bufs[(l + 1) & 1],
                                            l, out);
    }
}